// round 4
// baseline (speedup 1.0000x reference)
#include <cuda_runtime.h>

// LocalCosineSimilarity: fused channel-reduce + separable 11x11 box sum + finalize.
// x, y: [8, 3, 1024, 1024] f32.  out: [8, 1024, 1024] f32.

#define IMG_W   1024
#define IMG_H   1024
#define KW      11
#define RAD     5
#define TILE_W  64
#define TILE_H  54
#define REG_W   74            // TILE_W + 2*RAD
#define REG_H   64            // TILE_H + 2*RAD  (exactly 64 -> 64x4 = 256 horiz work items)
#define SSTR    75            // padded row stride in smem
#define PLANE   (REG_H * SSTR)
#define SMEM_BYTES (3 * PLANE * sizeof(float))
#define NTHREADS 256

__global__ void __launch_bounds__(NTHREADS, 3)
lcs_kernel(const float* __restrict__ xg, const float* __restrict__ yg,
           float* __restrict__ outg)
{
    extern __shared__ float smem[];   // 3 planes: xx, yy, xy

    const int tid = threadIdx.x;
    const int gx0 = blockIdx.x * TILE_W;
    const int gy0 = blockIdx.y * TILE_H;
    const int b   = blockIdx.z;

    const size_t HW = (size_t)IMG_W * IMG_H;
    const float* xb = xg + (size_t)b * 3 * HW;
    const float* yb = yg + (size_t)b * 3 * HW;

    // ---------------- Phase 1: load region, channel-reduce products ----------------
    for (int idx = tid; idx < REG_H * REG_W; idx += NTHREADS) {
        const int r = idx / REG_W;
        const int c = idx - r * REG_W;
        const int gy = gy0 - RAD + r;
        const int gx = gx0 - RAD + c;
        float xx = 0.f, yy = 0.f, xy = 0.f;
        if ((unsigned)gy < (unsigned)IMG_H && (unsigned)gx < (unsigned)IMG_W) {
            const size_t base = (size_t)gy * IMG_W + gx;
            #pragma unroll
            for (int ch = 0; ch < 3; ++ch) {
                const float xv = __ldg(xb + (size_t)ch * HW + base);
                const float yv = __ldg(yb + (size_t)ch * HW + base);
                xx = fmaf(xv, xv, xx);
                yy = fmaf(yv, yv, yy);
                xy = fmaf(xv, yv, xy);
            }
        }
        const int so = r * SSTR + c;
        smem[0 * PLANE + so] = xx;
        smem[1 * PLANE + so] = yy;
        smem[2 * PLANE + so] = xy;
    }
    __syncthreads();

    // ---------------- Phase 2: horizontal box sum, IN-PLACE via register staging ----
    // Work item: (row r = tid&63, output-col segment of 16 starting at (tid>>6)*16).
    // Each thread needs original prod cols [c0, c0+25]; other threads overwrite part
    // of that range, so stage into registers, barrier, then write back sliding sums.
    {
        const int r  = tid & 63;
        const int c0 = (tid >> 6) * 16;
        float* row0 = smem + r * SSTR;

        #pragma unroll
        for (int a = 0; a < 3; ++a) {
            float* row = row0 + a * PLANE;
            float v[26];
            #pragma unroll
            for (int k = 0; k < 26; ++k) v[k] = row[c0 + k];
            __syncthreads();

            float s = 0.f;
            #pragma unroll
            for (int k = 0; k < KW; ++k) s += v[k];
            #pragma unroll
            for (int j = 0; j < 16; ++j) {
                row[c0 + j] = s;
                if (j < 15) s += v[j + KW] - v[j];
            }
            __syncthreads();
        }
    }

    // ---------------- Phase 3: vertical box sum (sliding) + finalize + store -------
    {
        const int c    = tid & 63;
        const int jseg = tid >> 6;            // 0..3
        const int j0   = jseg * 14;
        const int jn   = min(14, TILE_H - j0); // 14,14,14,12

        const float* h0 = smem + 0 * PLANE + c;
        const float* h1 = smem + 1 * PLANE + c;
        const float* h2 = smem + 2 * PLANE + c;

        float sx = 0.f, sy = 0.f, sxy = 0.f;
        #pragma unroll
        for (int k = 0; k < KW; ++k) {
            const int rr = (j0 + k) * SSTR;
            sx  += h0[rr];
            sy  += h1[rr];
            sxy += h2[rr];
        }

        const int gx = gx0 + c;
        float* outb = outg + (size_t)b * HW;
        for (int j = 0; j < jn; ++j) {
            const int gy = gy0 + j0 + j;
            if (gy < IMG_H) {
                const float denom = sqrtf(sx) * sqrtf(sy) + 1e-6f;
                outb[(size_t)gy * IMG_W + gx] = sxy / denom;
            }
            if (j + 1 < jn) {
                const int rs = (j0 + j) * SSTR;
                const int ra = (j0 + j + KW) * SSTR;
                sx  += h0[ra] - h0[rs];
                sy  += h1[ra] - h1[rs];
                sxy += h2[ra] - h2[rs];
            }
        }
    }
}

extern "C" void kernel_launch(void* const* d_in, const int* in_sizes, int n_in,
                              void* d_out, int out_size)
{
    const float* x = (const float*)d_in[0];
    const float* y = (const float*)d_in[1];
    float* out = (float*)d_out;

    cudaFuncSetAttribute(lcs_kernel, cudaFuncAttributeMaxDynamicSharedMemorySize,
                         (int)SMEM_BYTES);

    dim3 grid(IMG_W / TILE_W,                       // 16
              (IMG_H + TILE_H - 1) / TILE_H,        // 19
              8);                                    // batch
    lcs_kernel<<<grid, NTHREADS, SMEM_BYTES>>>(x, y, out);
}